// round 2
// baseline (speedup 1.0000x reference)
#include <cuda_runtime.h>
#include <math.h>

#define BB 4
#define NN 4096
#define EE 256
#define FF 256
#define MAXE 50
#define HH1 128
#define HH2 64
#define SCALE 0.0625f   // 1/sqrt(256)

// ---------------- device scratch (static: no allocations allowed) ----------------
__device__ float g_xp[BB * NN * FF];   // x @ Wn_w + Wn_b      (16 MB)
__device__ float g_xw[BB * NN * FF];   // x @ weight + bias    (16 MB)
__device__ float g_ctx[BB * 64];       // context MLP output per (b, e<50)
__device__ float g_valid[64];          // deg > 1 flag per edge

// =================================================================================
// Kernel 1: per-hyperedge stats + context MLP.  One block per edge (50 blocks).
// =================================================================================
__global__ void __launch_bounds__(256) edge_kernel(
    const float* __restrict__ x, const int* __restrict__ H,
    const float* __restrict__ m1w, const float* __restrict__ m1b,
    const float* __restrict__ m2w, const float* __restrict__ m2b,
    const float* __restrict__ m3w, const float* __restrict__ m3b) {
  __shared__ float mask[NN];
  __shared__ float red[256];
  __shared__ float meanS[BB][FF];
  __shared__ float h1S[BB][HH1];
  __shared__ float h2S[BB][HH2];
  const int e = blockIdx.x;
  const int t = threadIdx.x;

  // load incidence column into smem, compute degree
  float dsum = 0.f;
  for (int n = t; n < NN; n += 256) {
    float m = (float)H[n * EE + e];
    mask[n] = m;
    dsum += m;
  }
  red[t] = dsum;
  __syncthreads();
  for (int s = 128; s > 0; s >>= 1) {
    if (t < s) red[t] += red[t + s];
    __syncthreads();
  }
  const float deg = red[0];

  // mean of member-node features; thread t owns feature f = t
  float a0 = 0.f, a1 = 0.f, a2 = 0.f, a3 = 0.f;
  for (int n = 0; n < NN; n++) {
    if (mask[n] != 0.f) {
      a0 += x[(size_t)(0 * NN + n) * FF + t];
      a1 += x[(size_t)(1 * NN + n) * FF + t];
      a2 += x[(size_t)(2 * NN + n) * FF + t];
      a3 += x[(size_t)(3 * NN + n) * FF + t];
    }
  }
  const float inv = 1.f / fmaxf(deg, 1.f);
  meanS[0][t] = a0 * inv; meanS[1][t] = a1 * inv;
  meanS[2][t] = a2 * inv; meanS[3][t] = a3 * inv;
  __syncthreads();

  // MLP_context: 256 -> 128 -> 64 -> 1 (relu, relu, linear)
  if (t < HH1) {
    for (int b = 0; b < BB; b++) {
      float s = m1b[t];
      for (int f = 0; f < FF; f++) s += meanS[b][f] * m1w[f * HH1 + t];
      h1S[b][t] = fmaxf(s, 0.f);
    }
  }
  __syncthreads();
  if (t < HH2) {
    for (int b = 0; b < BB; b++) {
      float s = m2b[t];
      for (int p = 0; p < HH1; p++) s += h1S[b][p] * m2w[p * HH2 + t];
      h2S[b][t] = fmaxf(s, 0.f);
    }
  }
  __syncthreads();
  if (t < BB) {
    float s = m3b[0];
    for (int j = 0; j < HH2; j++) s += h2S[t][j] * m3w[j];
    g_ctx[t * 64 + e] = s;
  }
  if (t == 0) g_valid[e] = (deg > 1.f) ? 1.f : 0.f;
}

// =================================================================================
// Kernel 2: adaptive node-hyperedge weights -> out[:, :, 0:256].
// One block per (n, b), 256 threads (thread t writes column e = t).
// =================================================================================
__global__ void __launch_bounds__(256) aw_kernel(
    const float* __restrict__ x, const int* __restrict__ H,
    const float* __restrict__ cw, const float* __restrict__ cb,
    const float* __restrict__ hb, const float* __restrict__ alpha,
    float* __restrict__ out) {
  const int n = blockIdx.x, b = blockIdx.y, t = threadIdx.x;
  __shared__ float red[256];
  red[t] = x[(size_t)(b * NN + n) * FF + t] * cw[t];
  __syncthreads();
  for (int s = 128; s > 0; s >>= 1) {
    if (t < s) red[t] += red[t + s];
    __syncthreads();
  }
  const float compat = red[0] + cb[0];
  float o = 0.f;
  if (t < MAXE) {
    if (H[n * EE + t] != 0 && g_valid[t] != 0.f) {
      float z = compat + hb[0] + alpha[0] * g_ctx[b * 64 + t];
      o = 1.f / (1.f + __expf(-z));
    }
  }
  out[(size_t)(b * NN + n) * (EE + FF) + t] = o;
}

// =================================================================================
// Kernel 3: SGEMM  C[16384,256] = X @ W + bvec.  grid.z selects (Wn_w -> g_xp) or
// (weight -> g_xw).  64x64 tile / block, 4x4 micro-tile / thread, full K in smem.
// =================================================================================
#define GEMM_SMEM ((256 * 65 + 256 * 64) * 4)

__global__ void __launch_bounds__(256, 1) gemm_kernel(
    const float* __restrict__ x,
    const float* __restrict__ wn_w, const float* __restrict__ wn_b,
    const float* __restrict__ weight, const float* __restrict__ bias) {
  extern __shared__ float sm[];
  float* Xs = sm;              // [256][65]  K-major, transposed X tile
  float* Ws = sm + 256 * 65;   // [256][64]  K-major W tile
  const float* W; const float* bv; float* dst;
  if (blockIdx.z == 0) { W = wn_w;   bv = wn_b; dst = g_xp; }
  else                 { W = weight; bv = bias; dst = g_xw; }
  const int n0 = blockIdx.x * 64, m0 = blockIdx.y * 64;
  const int t = threadIdx.x, tx = t & 15, ty = t >> 4;

  // load X tile transposed: thread t owns feature f = t, loops rows
  for (int i = 0; i < 64; i++)
    Xs[t * 65 + i] = x[(size_t)(m0 + i) * FF + t];
  // load W tile (k-major natural)
  for (int i = 0; i < 64; i++) {
    int idx = t + i * 256; int j = idx & 63; int k = idx >> 6;
    Ws[k * 64 + j] = W[(size_t)k * FF + n0 + j];
  }
  __syncthreads();

  float acc[4][4] = {};
  #pragma unroll 8
  for (int k = 0; k < 256; k++) {
    const float* xr = Xs + k * 65;
    const float* wr = Ws + k * 64;
    float q0 = xr[ty], q1 = xr[ty + 16], q2 = xr[ty + 32], q3 = xr[ty + 48];
    float w0 = wr[tx], w1 = wr[tx + 16], w2 = wr[tx + 32], w3 = wr[tx + 48];
    acc[0][0] += q0 * w0; acc[0][1] += q0 * w1; acc[0][2] += q0 * w2; acc[0][3] += q0 * w3;
    acc[1][0] += q1 * w0; acc[1][1] += q1 * w1; acc[1][2] += q1 * w2; acc[1][3] += q1 * w3;
    acc[2][0] += q2 * w0; acc[2][1] += q2 * w1; acc[2][2] += q2 * w2; acc[2][3] += q2 * w3;
    acc[3][0] += q3 * w0; acc[3][1] += q3 * w1; acc[3][2] += q3 * w2; acc[3][3] += q3 * w3;
  }
  #pragma unroll
  for (int a = 0; a < 4; a++) {
    const int row = m0 + ty + 16 * a;
    #pragma unroll
    for (int c = 0; c < 4; c++) {
      const int col = n0 + tx + 16 * c;
      dst[(size_t)row * FF + col] = acc[a][c] + bv[col];
    }
  }
}

// =================================================================================
// Kernel 4: flash attention, no max-subtraction (logits are tiny by construction).
// One block per (64-row tile, batch).  Per column tile of 64:
//   S = Q @ K^T  (regs, 4x4/thread) -> P = exp(S/16) -> smem -> O += P @ V.
// Unnormalized accumulation; divide by rowsum at the end.  bias already in xw.
// =================================================================================
#define FLASH_SMEM ((256 * 65 * 2 + 64 * 256 + 64 * 65 + 64) * 4)

__global__ void __launch_bounds__(256, 1) flash_kernel(float* __restrict__ out) {
  extern __shared__ float sm[];
  float* Qs  = sm;                             // [256][65] transposed
  float* Ks  = Qs + 256 * 65;                  // [256][65] transposed
  float* Vs  = Ks + 256 * 65;                  // [64][256] row-major
  float* Ps  = Vs + 64 * 256;                  // [64][65]
  float* rsS = Ps + 64 * 65;                   // [64]
  const int b = blockIdx.y;
  const int row0 = blockIdx.x * 64;
  const int t = threadIdx.x, tx = t & 15, ty = t >> 4;
  const float* xp = g_xp + (size_t)b * NN * FF;
  const float* xw = g_xw + (size_t)b * NN * FF;

  // resident Q tile (transposed, K-major)
  for (int i = 0; i < 64; i++)
    Qs[t * 65 + i] = xp[(size_t)(row0 + i) * FF + t];

  float o[4][16];
  #pragma unroll
  for (int a = 0; a < 4; a++)
    #pragma unroll
    for (int w = 0; w < 16; w++) o[a][w] = 0.f;
  float rsum[4] = {0.f, 0.f, 0.f, 0.f};

  for (int j0 = 0; j0 < NN; j0 += 64) {
    __syncthreads();  // previous tile's Ps/Vs reads done before overwrite
    for (int i = 0; i < 64; i++)
      Ks[t * 65 + i] = xp[(size_t)(j0 + i) * FF + t];
    {
      const float4* src = (const float4*)(xw + (size_t)j0 * FF);
      float4* dv = (float4*)Vs;
      for (int i = t; i < 64 * FF / 4; i += 256) dv[i] = src[i];
    }
    __syncthreads();

    // ---- S = Q @ K^T : thread owns rows {ty+16a}, cols {tx+16c} ----
    float acc[4][4] = {};
    #pragma unroll 8
    for (int k = 0; k < 256; k++) {
      const float* qr = Qs + k * 65;
      const float* kr = Ks + k * 65;
      float q0 = qr[ty], q1 = qr[ty + 16], q2 = qr[ty + 32], q3 = qr[ty + 48];
      float c0 = kr[tx], c1 = kr[tx + 16], c2 = kr[tx + 32], c3 = kr[tx + 48];
      acc[0][0] += q0 * c0; acc[0][1] += q0 * c1; acc[0][2] += q0 * c2; acc[0][3] += q0 * c3;
      acc[1][0] += q1 * c0; acc[1][1] += q1 * c1; acc[1][2] += q1 * c2; acc[1][3] += q1 * c3;
      acc[2][0] += q2 * c0; acc[2][1] += q2 * c1; acc[2][2] += q2 * c2; acc[2][3] += q2 * c3;
      acc[3][0] += q3 * c0; acc[3][1] += q3 * c1; acc[3][2] += q3 * c2; acc[3][3] += q3 * c3;
    }

    // ---- P = exp(S * scale); stage to smem; accumulate rowsums ----
    #pragma unroll
    for (int a = 0; a < 4; a++) {
      float p0 = __expf(acc[a][0] * SCALE);
      float p1 = __expf(acc[a][1] * SCALE);
      float p2 = __expf(acc[a][2] * SCALE);
      float p3 = __expf(acc[a][3] * SCALE);
      rsum[a] += (p0 + p1) + (p2 + p3);
      float* pr = Ps + (ty + 16 * a) * 65;
      pr[tx] = p0; pr[tx + 16] = p1; pr[tx + 32] = p2; pr[tx + 48] = p3;
    }
    __syncthreads();

    // ---- O += P @ V : thread owns rows {ty+16a}, f-cols {4tx+64w+q} ----
    for (int j = 0; j < 64; j++) {
      float p0 = Ps[ty * 65 + j];
      float p1 = Ps[(ty + 16) * 65 + j];
      float p2 = Ps[(ty + 32) * 65 + j];
      float p3 = Ps[(ty + 48) * 65 + j];
      const float4* vr = (const float4*)(Vs + j * FF);
      #pragma unroll
      for (int w = 0; w < 4; w++) {
        float4 v = vr[tx + 16 * w];
        o[0][4 * w + 0] += p0 * v.x; o[0][4 * w + 1] += p0 * v.y;
        o[0][4 * w + 2] += p0 * v.z; o[0][4 * w + 3] += p0 * v.w;
        o[1][4 * w + 0] += p1 * v.x; o[1][4 * w + 1] += p1 * v.y;
        o[1][4 * w + 2] += p1 * v.z; o[1][4 * w + 3] += p1 * v.w;
        o[2][4 * w + 0] += p2 * v.x; o[2][4 * w + 1] += p2 * v.y;
        o[2][4 * w + 2] += p2 * v.z; o[2][4 * w + 3] += p2 * v.w;
        o[3][4 * w + 0] += p3 * v.x; o[3][4 * w + 1] += p3 * v.y;
        o[3][4 * w + 2] += p3 * v.z; o[3][4 * w + 3] += p3 * v.w;
      }
    }
  }

  // ---- reduce rowsums across the 16 tx threads sharing each row ----
  __syncthreads();
  #pragma unroll
  for (int a = 0; a < 4; a++) Ps[(ty + 16 * a) * 65 + tx] = rsum[a];
  __syncthreads();
  if (t < 64) {
    float s = 0.f;
    for (int i = 0; i < 16; i++) s += Ps[t * 65 + i];
    rsS[t] = s;
  }
  __syncthreads();

  // ---- normalize and write out[:, :, 256:512] ----
  float* ob = out + ((size_t)(b * NN + row0)) * (EE + FF) + EE;
  #pragma unroll
  for (int a = 0; a < 4; a++) {
    const float inv = 1.f / rsS[ty + 16 * a];
    float* orow = ob + (size_t)(ty + 16 * a) * (EE + FF);
    #pragma unroll
    for (int w = 0; w < 4; w++) {
      float4 v;
      v.x = o[a][4 * w + 0] * inv; v.y = o[a][4 * w + 1] * inv;
      v.z = o[a][4 * w + 2] * inv; v.w = o[a][4 * w + 3] * inv;
      *(float4*)(orow + 4 * tx + 64 * w) = v;
    }
  }
}

// =================================================================================
extern "C" void kernel_launch(void* const* d_in, const int* in_sizes, int n_in,
                              void* d_out, int out_size) {
  const float* x      = (const float*)d_in[0];
  const int*   H      = (const int*)  d_in[1];
  const float* weight = (const float*)d_in[2];
  const float* bias   = (const float*)d_in[3];
  const float* wn_w   = (const float*)d_in[4];
  const float* wn_b   = (const float*)d_in[5];
  const float* m1w    = (const float*)d_in[6];
  const float* m1b    = (const float*)d_in[7];
  const float* m2w    = (const float*)d_in[8];
  const float* m2b    = (const float*)d_in[9];
  const float* m3w    = (const float*)d_in[10];
  const float* m3b    = (const float*)d_in[11];
  const float* cw     = (const float*)d_in[12];
  const float* cb     = (const float*)d_in[13];
  const float* hb     = (const float*)d_in[14];
  const float* alpha  = (const float*)d_in[15];
  float* out = (float*)d_out;

  cudaFuncSetAttribute(gemm_kernel,  cudaFuncAttributeMaxDynamicSharedMemorySize, GEMM_SMEM);
  cudaFuncSetAttribute(flash_kernel, cudaFuncAttributeMaxDynamicSharedMemorySize, FLASH_SMEM);

  edge_kernel<<<MAXE, 256>>>(x, H, m1w, m1b, m2w, m2b, m3w, m3b);
  aw_kernel<<<dim3(NN, BB), 256>>>(x, H, cw, cb, hb, alpha, out);
  gemm_kernel<<<dim3(FF / 64, (BB * NN) / 64, 2), 256, GEMM_SMEM>>>(x, wn_w, wn_b, weight, bias);
  flash_kernel<<<dim3(NN / 64, BB), 256, FLASH_SMEM>>>(out);
}

// round 5
// speedup vs baseline: 1.3735x; 1.3735x over previous
#include <cuda_runtime.h>
#include <mma.h>
#include <math.h>

using namespace nvcuda;

#define BB 4
#define NN 4096
#define EE 256
#define FF 256
#define MAXE 50
#define HH1 128
#define HH2 64
#define SCALE 0.0625f   // 1/sqrt(256)

// ---------------- device scratch ----------------
__device__ float g_xp[BB * NN * FF];   // x @ Wn_w + Wn_b
__device__ float g_xw[BB * NN * FF];   // x @ weight + bias
__device__ float g_ctx[BB * 64];
__device__ float g_valid[64];

// ================= Kernel 1: hyperedge stats + context MLP =================
__global__ void __launch_bounds__(256) edge_kernel(
    const float* __restrict__ x, const int* __restrict__ H,
    const float* __restrict__ m1w, const float* __restrict__ m1b,
    const float* __restrict__ m2w, const float* __restrict__ m2b,
    const float* __restrict__ m3w, const float* __restrict__ m3b) {
  __shared__ float mask[NN];
  __shared__ float red[256];
  __shared__ float meanS[BB][FF];
  __shared__ float h1S[BB][HH1];
  __shared__ float h2S[BB][HH2];
  const int e = blockIdx.x, t = threadIdx.x;
  float dsum = 0.f;
  for (int n = t; n < NN; n += 256) {
    float m = (float)H[n * EE + e];
    mask[n] = m;
    dsum += m;
  }
  red[t] = dsum;
  __syncthreads();
  for (int s = 128; s > 0; s >>= 1) {
    if (t < s) red[t] += red[t + s];
    __syncthreads();
  }
  const float deg = red[0];
  float a0 = 0.f, a1 = 0.f, a2 = 0.f, a3 = 0.f;
  for (int n = 0; n < NN; n++) {
    if (mask[n] != 0.f) {
      a0 += x[(size_t)(0 * NN + n) * FF + t];
      a1 += x[(size_t)(1 * NN + n) * FF + t];
      a2 += x[(size_t)(2 * NN + n) * FF + t];
      a3 += x[(size_t)(3 * NN + n) * FF + t];
    }
  }
  const float inv = 1.f / fmaxf(deg, 1.f);
  meanS[0][t] = a0 * inv; meanS[1][t] = a1 * inv;
  meanS[2][t] = a2 * inv; meanS[3][t] = a3 * inv;
  __syncthreads();
  if (t < HH1) {
    for (int b = 0; b < BB; b++) {
      float s = m1b[t];
      for (int f = 0; f < FF; f++) s += meanS[b][f] * m1w[f * HH1 + t];
      h1S[b][t] = fmaxf(s, 0.f);
    }
  }
  __syncthreads();
  if (t < HH2) {
    for (int b = 0; b < BB; b++) {
      float s = m2b[t];
      for (int p = 0; p < HH1; p++) s += h1S[b][p] * m2w[p * HH2 + t];
      h2S[b][t] = fmaxf(s, 0.f);
    }
  }
  __syncthreads();
  if (t < BB) {
    float s = m3b[0];
    for (int j = 0; j < HH2; j++) s += h2S[t][j] * m3w[j];
    g_ctx[t * 64 + e] = s;
  }
  if (t == 0) g_valid[e] = (deg > 1.f) ? 1.f : 0.f;
}

// ================= Kernel 2: adaptive weights -> out[:, :, 0:256] =================
__global__ void __launch_bounds__(256) aw_kernel(
    const float* __restrict__ x, const int* __restrict__ H,
    const float* __restrict__ cw, const float* __restrict__ cb,
    const float* __restrict__ hb, const float* __restrict__ alpha,
    float* __restrict__ out) {
  const int n = blockIdx.x, b = blockIdx.y, t = threadIdx.x;
  __shared__ float red[256];
  red[t] = x[(size_t)(b * NN + n) * FF + t] * cw[t];
  __syncthreads();
  for (int s = 128; s > 0; s >>= 1) {
    if (t < s) red[t] += red[t + s];
    __syncthreads();
  }
  const float compat = red[0] + cb[0];
  float o = 0.f;
  if (t < MAXE) {
    if (H[n * EE + t] != 0 && g_valid[t] != 0.f) {
      float z = compat + hb[0] + alpha[0] * g_ctx[b * 64 + t];
      o = 1.f / (1.f + __expf(-z));
    }
  }
  out[(size_t)(b * NN + n) * (EE + FF) + t] = o;
}

// ================= Kernel 3: SGEMM  xp = x@Wn_w + b ; xw = x@weight + b ============
#define GEMM_SMEM ((256 * 65 + 256 * 64) * 4)
__global__ void __launch_bounds__(256, 1) gemm_kernel(
    const float* __restrict__ x,
    const float* __restrict__ wn_w, const float* __restrict__ wn_b,
    const float* __restrict__ weight, const float* __restrict__ bias) {
  extern __shared__ float sm[];
  float* Xs = sm;
  float* Ws = sm + 256 * 65;
  const float* W; const float* bv; float* dst;
  if (blockIdx.z == 0) { W = wn_w;   bv = wn_b; dst = g_xp; }
  else                 { W = weight; bv = bias; dst = g_xw; }
  const int n0 = blockIdx.x * 64, m0 = blockIdx.y * 64;
  const int t = threadIdx.x, tx = t & 15, ty = t >> 4;
  for (int i = 0; i < 64; i++)
    Xs[t * 65 + i] = x[(size_t)(m0 + i) * FF + t];
  for (int i = 0; i < 64; i++) {
    int idx = t + i * 256; int j = idx & 63; int k = idx >> 6;
    Ws[k * 64 + j] = W[(size_t)k * FF + n0 + j];
  }
  __syncthreads();
  float acc[4][4] = {};
  #pragma unroll 8
  for (int k = 0; k < 256; k++) {
    const float* xr = Xs + k * 65;
    const float* wr = Ws + k * 64;
    float q0 = xr[ty], q1 = xr[ty + 16], q2 = xr[ty + 32], q3 = xr[ty + 48];
    float w0 = wr[tx], w1 = wr[tx + 16], w2 = wr[tx + 32], w3 = wr[tx + 48];
    acc[0][0] += q0 * w0; acc[0][1] += q0 * w1; acc[0][2] += q0 * w2; acc[0][3] += q0 * w3;
    acc[1][0] += q1 * w0; acc[1][1] += q1 * w1; acc[1][2] += q1 * w2; acc[1][3] += q1 * w3;
    acc[2][0] += q2 * w0; acc[2][1] += q2 * w1; acc[2][2] += q2 * w2; acc[2][3] += q2 * w3;
    acc[3][0] += q3 * w0; acc[3][1] += q3 * w1; acc[3][2] += q3 * w2; acc[3][3] += q3 * w3;
  }
  #pragma unroll
  for (int a = 0; a < 4; a++) {
    const int row = m0 + ty + 16 * a;
    #pragma unroll
    for (int c = 0; c < 4; c++) {
      const int col = n0 + tx + 16 * c;
      dst[(size_t)row * FF + col] = acc[a][c] + bv[col];
    }
  }
}

// ================= Kernel 4: WMMA tf32 flash attention =================
// 64 Q-rows per CTA, j-tiles of 64.  8 warps: warp w -> row strip (w&3)*16,
// col half (w>>2).  S = Q K^T (K col_major B), exp in smem, O += P V
// (V row_major B), unnormalized; divide by rowsum at the end.
#define LDQ 264
#define LDP 68
// floats: Q + K + V tiles, P tile, rowsum partials [2][64]
#define FL_FLOATS (3 * 64 * LDQ + 64 * LDP + 128)
#define FL_SMEM (FL_FLOATS * 4)

__global__ void __launch_bounds__(256, 1) flash_wmma(float* __restrict__ out) {
  extern __shared__ float sm[];
  float* Qs = sm;                    // [64][LDQ]
  float* Ks = Qs + 64 * LDQ;         // [64][LDQ]
  float* Vs = Ks + 64 * LDQ;         // [64][LDQ]
  float* Ps = Vs + 64 * LDQ;         // [64][LDP]
  float* rsp = Ps + 64 * LDP;        // [2][64] rowsum partials
  const int b = blockIdx.y, row0 = blockIdx.x * 64;
  const int t = threadIdx.x, w = t >> 5, lane = t & 31;
  const int wr = w & 3, wc = w >> 2;
  const float* xp = g_xp + (size_t)b * NN * FF;
  const float* xw = g_xw + (size_t)b * NN * FF;

  // resident Q tile
  for (int i = t; i < 64 * 64; i += 256) {
    int r = i >> 6, c = (i & 63) * 4;
    *(float4*)(Qs + r * LDQ + c) = *(const float4*)(xp + (size_t)(row0 + r) * FF + c);
  }

  wmma::fragment<wmma::accumulator, 16, 16, 8, float> oacc[8];
  #pragma unroll
  for (int i = 0; i < 8; i++) wmma::fill_fragment(oacc[i], 0.f);
  float rsum = 0.f;  // lanes 0..15: partial rowsum of row wr*16+lane (this col half)

  for (int j0 = 0; j0 < NN; j0 += 64) {
    __syncthreads();
    for (int i = t; i < 64 * 64; i += 256) {
      int r = i >> 6, c = (i & 63) * 4;
      *(float4*)(Ks + r * LDQ + c) = *(const float4*)(xp + (size_t)(j0 + r) * FF + c);
      *(float4*)(Vs + r * LDQ + c) = *(const float4*)(xw + (size_t)(j0 + r) * FF + c);
    }
    __syncthreads();

    // ---- S = Q K^T : strip rows wr*16, cols wc*32 + {0,16} ----
    wmma::fragment<wmma::accumulator, 16, 16, 8, float> sacc[2];
    wmma::fill_fragment(sacc[0], 0.f);
    wmma::fill_fragment(sacc[1], 0.f);
    for (int k = 0; k < 256; k += 8) {
      wmma::fragment<wmma::matrix_a, 16, 16, 8, wmma::precision::tf32, wmma::row_major> af;
      wmma::load_matrix_sync(af, Qs + wr * 16 * LDQ + k, LDQ);
      #pragma unroll
      for (int i = 0; i < af.num_elements; i++) af.x[i] = wmma::__float_to_tf32(af.x[i]);
      #pragma unroll
      for (int nt = 0; nt < 2; nt++) {
        wmma::fragment<wmma::matrix_b, 16, 16, 8, wmma::precision::tf32, wmma::col_major> bf;
        wmma::load_matrix_sync(bf, Ks + (wc * 32 + nt * 16) * LDQ + k, LDQ);
        #pragma unroll
        for (int i = 0; i < bf.num_elements; i++) bf.x[i] = wmma::__float_to_tf32(bf.x[i]);
        wmma::mma_sync(sacc[nt], af, bf, sacc[nt]);
      }
    }
    wmma::store_matrix_sync(Ps + wr * 16 * LDP + wc * 32, sacc[0], LDP, wmma::mem_row_major);
    wmma::store_matrix_sync(Ps + wr * 16 * LDP + wc * 32 + 16, sacc[1], LDP, wmma::mem_row_major);
    __syncwarp();

    // ---- exp in place + deterministic rowsum (own strip only) ----
    {
      const int r = lane & 15, ch = lane >> 4;
      float* pr = Ps + (wr * 16 + r) * LDP + wc * 32 + ch * 16;
      float s = 0.f;
      #pragma unroll
      for (int c2 = 0; c2 < 16; c2++) {
        float e = __expf(pr[c2] * SCALE);
        pr[c2] = e;
        s += e;
      }
      s += __shfl_xor_sync(0xffffffff, s, 16);
      if (lane < 16) rsum += s;
    }
    __syncthreads();

    // ---- O += P V : A rows wr*16 (k=0..63), B = V row_major, n-tiles wc*128.. ----
    for (int k = 0; k < 64; k += 8) {
      wmma::fragment<wmma::matrix_a, 16, 16, 8, wmma::precision::tf32, wmma::row_major> af;
      wmma::load_matrix_sync(af, Ps + wr * 16 * LDP + k, LDP);
      #pragma unroll
      for (int i = 0; i < af.num_elements; i++) af.x[i] = wmma::__float_to_tf32(af.x[i]);
      #pragma unroll
      for (int nt = 0; nt < 8; nt++) {
        wmma::fragment<wmma::matrix_b, 16, 16, 8, wmma::precision::tf32, wmma::row_major> bf;
        wmma::load_matrix_sync(bf, Vs + k * LDQ + wc * 128 + nt * 16, LDQ);
        #pragma unroll
        for (int i = 0; i < bf.num_elements; i++) bf.x[i] = wmma::__float_to_tf32(bf.x[i]);
        wmma::mma_sync(oacc[nt], af, bf, oacc[nt]);
      }
    }
  }

  // ---- combine rowsum halves ----
  if (lane < 16) rsp[wc * 64 + wr * 16 + lane] = rsum;
  __syncthreads();

  // ---- normalize + write out[:, :, 256:512]; reuse Ps as per-warp staging ----
  float* scr = Ps + w * 340;  // 16x16 tile staged with ld 20 (320 floats)
  const int r = lane >> 1, c0 = (lane & 1) * 8;
  const float inv = 1.f / (rsp[wr * 16 + r] + rsp[64 + wr * 16 + r]);
  float* orow = out + (size_t)(b * NN + row0 + wr * 16 + r) * (EE + FF) + EE + wc * 128;
  #pragma unroll
  for (int nt = 0; nt < 8; nt++) {
    wmma::store_matrix_sync(scr, oacc[nt], 20, wmma::mem_row_major);
    __syncwarp();
    #pragma unroll
    for (int c2 = 0; c2 < 8; c2++)
      orow[nt * 16 + c0 + c2] = scr[r * 20 + c0 + c2] * inv;
    __syncwarp();
  }
}

// =================================================================================
extern "C" void kernel_launch(void* const* d_in, const int* in_sizes, int n_in,
                              void* d_out, int out_size) {
  const float* x      = (const float*)d_in[0];
  const int*   H      = (const int*)  d_in[1];
  const float* weight = (const float*)d_in[2];
  const float* bias   = (const float*)d_in[3];
  const float* wn_w   = (const float*)d_in[4];
  const float* wn_b   = (const float*)d_in[5];
  const float* m1w    = (const float*)d_in[6];
  const float* m1b    = (const float*)d_in[7];
  const float* m2w    = (const float*)d_in[8];
  const float* m2b    = (const float*)d_in[9];
  const float* m3w    = (const float*)d_in[10];
  const float* m3b    = (const float*)d_in[11];
  const float* cw     = (const float*)d_in[12];
  const float* cb     = (const float*)d_in[13];
  const float* hb     = (const float*)d_in[14];
  const float* alpha  = (const float*)d_in[15];
  float* out = (float*)d_out;

  cudaFuncSetAttribute(gemm_kernel, cudaFuncAttributeMaxDynamicSharedMemorySize, GEMM_SMEM);
  cudaFuncSetAttribute(flash_wmma, cudaFuncAttributeMaxDynamicSharedMemorySize, FL_SMEM);

  edge_kernel<<<MAXE, 256>>>(x, H, m1w, m1b, m2w, m2b, m3w, m3b);
  aw_kernel<<<dim3(NN, BB), 256>>>(x, H, cw, cb, hb, alpha, out);
  gemm_kernel<<<dim3(FF / 64, (BB * NN) / 64, 2), 256, GEMM_SMEM>>>(x, wn_w, wn_b, weight, bias);
  flash_wmma<<<dim3(NN / 64, BB), 256, FL_SMEM>>>(out);
}

// round 6
// speedup vs baseline: 1.6257x; 1.1836x over previous
#include <cuda_runtime.h>
#include <mma.h>
#include <math.h>
#include <cstdint>

using namespace nvcuda;

#define BB 4
#define NN 4096
#define EE 256
#define FF 256
#define MAXE 50
#define HH1 128
#define HH2 64
#define SCALE 0.0625f   // 1/sqrt(256)

// ---------------- device scratch ----------------
__device__ float g_xp[BB * NN * FF];   // tf32-rounded x @ Wn_w + Wn_b
__device__ float g_xw[BB * NN * FF];   // tf32-rounded x @ weight + bias
__device__ float g_ctx[BB * 64];
__device__ float g_valid[64];

// ---------------- cp.async helpers ----------------
__device__ __forceinline__ uint32_t smem_u32(const void* p) {
  uint32_t a;
  asm("{ .reg .u64 t; cvta.to.shared.u64 t, %1; cvt.u32.u64 %0, t; }" : "=r"(a) : "l"(p));
  return a;
}
__device__ __forceinline__ void cp16(uint32_t dst, const void* src) {
  asm volatile("cp.async.cg.shared.global [%0], [%1], 16;" ::"r"(dst), "l"(src));
}
#define CP_COMMIT() asm volatile("cp.async.commit_group;" ::: "memory")
#define CP_WAIT0()  asm volatile("cp.async.wait_group 0;" ::: "memory")

// ================= Kernel 1: hyperedge stats + context MLP =================
__global__ void __launch_bounds__(256) edge_kernel(
    const float* __restrict__ x, const int* __restrict__ H,
    const float* __restrict__ m1w, const float* __restrict__ m1b,
    const float* __restrict__ m2w, const float* __restrict__ m2b,
    const float* __restrict__ m3w, const float* __restrict__ m3b) {
  __shared__ float mask[NN];
  __shared__ float red[256];
  __shared__ float meanS[BB][FF];
  __shared__ float h1S[BB][HH1];
  __shared__ float h2S[BB][HH2];
  const int e = blockIdx.x, t = threadIdx.x;
  float dsum = 0.f;
  for (int n = t; n < NN; n += 256) {
    float m = (float)H[n * EE + e];
    mask[n] = m;
    dsum += m;
  }
  red[t] = dsum;
  __syncthreads();
  for (int s = 128; s > 0; s >>= 1) {
    if (t < s) red[t] += red[t + s];
    __syncthreads();
  }
  const float deg = red[0];
  float a0 = 0.f, a1 = 0.f, a2 = 0.f, a3 = 0.f;
  for (int n = 0; n < NN; n++) {
    if (mask[n] != 0.f) {
      a0 += x[(size_t)(0 * NN + n) * FF + t];
      a1 += x[(size_t)(1 * NN + n) * FF + t];
      a2 += x[(size_t)(2 * NN + n) * FF + t];
      a3 += x[(size_t)(3 * NN + n) * FF + t];
    }
  }
  const float inv = 1.f / fmaxf(deg, 1.f);
  meanS[0][t] = a0 * inv; meanS[1][t] = a1 * inv;
  meanS[2][t] = a2 * inv; meanS[3][t] = a3 * inv;
  __syncthreads();
  if (t < HH1) {
    for (int b = 0; b < BB; b++) {
      float s = m1b[t];
      for (int f = 0; f < FF; f++) s += meanS[b][f] * m1w[f * HH1 + t];
      h1S[b][t] = fmaxf(s, 0.f);
    }
  }
  __syncthreads();
  if (t < HH2) {
    for (int b = 0; b < BB; b++) {
      float s = m2b[t];
      for (int p = 0; p < HH1; p++) s += h1S[b][p] * m2w[p * HH2 + t];
      h2S[b][t] = fmaxf(s, 0.f);
    }
  }
  __syncthreads();
  if (t < BB) {
    float s = m3b[0];
    for (int j = 0; j < HH2; j++) s += h2S[t][j] * m3w[j];
    g_ctx[t * 64 + e] = s;
  }
  if (t == 0) g_valid[e] = (deg > 1.f) ? 1.f : 0.f;
}

// ================= Kernel 2: adaptive weights -> out[:, :, 0:256] =================
__global__ void __launch_bounds__(256) aw_kernel(
    const float* __restrict__ x, const int* __restrict__ H,
    const float* __restrict__ cw, const float* __restrict__ cb,
    const float* __restrict__ hb, const float* __restrict__ alpha,
    float* __restrict__ out) {
  const int n = blockIdx.x, b = blockIdx.y, t = threadIdx.x;
  __shared__ float red[256];
  red[t] = x[(size_t)(b * NN + n) * FF + t] * cw[t];
  __syncthreads();
  for (int s = 128; s > 0; s >>= 1) {
    if (t < s) red[t] += red[t + s];
    __syncthreads();
  }
  const float compat = red[0] + cb[0];
  float o = 0.f;
  if (t < MAXE) {
    if (H[n * EE + t] != 0 && g_valid[t] != 0.f) {
      float z = compat + hb[0] + alpha[0] * g_ctx[b * 64 + t];
      o = 1.f / (1.f + __expf(-z));
    }
  }
  out[(size_t)(b * NN + n) * (EE + FF) + t] = o;
}

// ================= Kernel 3: SGEMM; epilogue rounds result to tf32 ============
#define GEMM_SMEM ((256 * 65 + 256 * 64) * 4)
__global__ void __launch_bounds__(256, 1) gemm_kernel(
    const float* __restrict__ x,
    const float* __restrict__ wn_w, const float* __restrict__ wn_b,
    const float* __restrict__ weight, const float* __restrict__ bias) {
  extern __shared__ float sm[];
  float* Xs = sm;
  float* Ws = sm + 256 * 65;
  const float* W; const float* bv; float* dst;
  if (blockIdx.z == 0) { W = wn_w;   bv = wn_b; dst = g_xp; }
  else                 { W = weight; bv = bias; dst = g_xw; }
  const int n0 = blockIdx.x * 64, m0 = blockIdx.y * 64;
  const int t = threadIdx.x, tx = t & 15, ty = t >> 4;
  for (int i = 0; i < 64; i++)
    Xs[t * 65 + i] = x[(size_t)(m0 + i) * FF + t];
  for (int i = 0; i < 64; i++) {
    int idx = t + i * 256; int j = idx & 63; int k = idx >> 6;
    Ws[k * 64 + j] = W[(size_t)k * FF + n0 + j];
  }
  __syncthreads();
  float acc[4][4] = {};
  #pragma unroll 8
  for (int k = 0; k < 256; k++) {
    const float* xr = Xs + k * 65;
    const float* wr = Ws + k * 64;
    float q0 = xr[ty], q1 = xr[ty + 16], q2 = xr[ty + 32], q3 = xr[ty + 48];
    float w0 = wr[tx], w1 = wr[tx + 16], w2 = wr[tx + 32], w3 = wr[tx + 48];
    acc[0][0] += q0 * w0; acc[0][1] += q0 * w1; acc[0][2] += q0 * w2; acc[0][3] += q0 * w3;
    acc[1][0] += q1 * w0; acc[1][1] += q1 * w1; acc[1][2] += q1 * w2; acc[1][3] += q1 * w3;
    acc[2][0] += q2 * w0; acc[2][1] += q2 * w1; acc[2][2] += q2 * w2; acc[2][3] += q2 * w3;
    acc[3][0] += q3 * w0; acc[3][1] += q3 * w1; acc[3][2] += q3 * w2; acc[3][3] += q3 * w3;
  }
  #pragma unroll
  for (int a = 0; a < 4; a++) {
    const int row = m0 + ty + 16 * a;
    #pragma unroll
    for (int c = 0; c < 4; c++) {
      const int col = n0 + tx + 16 * c;
      dst[(size_t)row * FF + col] = wmma::__float_to_tf32(acc[a][c] + bv[col]);
    }
  }
}

// ================= Kernel 4: WMMA tf32 flash, cp.async pipelined =================
// 64 Q-rows/CTA, 64 j-tiles of 64.  8 warps: warp w -> row strip (w&3)*16,
// col half (w>>2).  Fixed-role buffers: Kb (K tiles), Vb (V tiles).
// V_j prefetch overlaps S compute; K_{j+1} prefetch overlaps PV compute.
// All smem data pre-rounded to tf32 -> no per-fragment conversions.
#define LDQ 264
#define LDP 68
#define FL_FLOATS (3 * 64 * LDQ + 64 * LDP + 128)
#define FL_SMEM (FL_FLOATS * 4)

__global__ void __launch_bounds__(256, 1) flash_wmma(float* __restrict__ out) {
  extern __shared__ float sm[];
  float* Qs = sm;                    // [64][LDQ]
  float* Kb = Qs + 64 * LDQ;         // [64][LDQ]
  float* Vb = Kb + 64 * LDQ;         // [64][LDQ]
  float* Ps = Vb + 64 * LDQ;         // [64][LDP]
  float* rsp = Ps + 64 * LDP;        // [2][64]
  const uint32_t qs_a = smem_u32(Qs), kb_a = smem_u32(Kb), vb_a = smem_u32(Vb);
  const int b = blockIdx.y, row0 = blockIdx.x * 64;
  const int t = threadIdx.x, w = t >> 5, lane = t & 31;
  const int wr = w & 3, wc = w >> 2;
  const float* xp = g_xp + (size_t)b * NN * FF;
  const float* xw = g_xw + (size_t)b * NN * FF;

  // async: resident Q tile + K tile 0 (one group)
  #pragma unroll
  for (int i = t; i < 64 * 64; i += 256) {
    const int r = i >> 6, c = (i & 63) * 4;
    const uint32_t off = (uint32_t)(r * LDQ + c) * 4;
    cp16(qs_a + off, xp + (size_t)(row0 + r) * FF + c);
    cp16(kb_a + off, xp + (size_t)r * FF + c);
  }
  CP_COMMIT();

  wmma::fragment<wmma::accumulator, 16, 16, 8, float> oacc[8];
  #pragma unroll
  for (int i = 0; i < 8; i++) wmma::fill_fragment(oacc[i], 0.f);
  float rsum = 0.f;  // lanes 0..15: partial rowsum (this col half)

  for (int tile = 0; tile < 64; tile++) {
    CP_WAIT0();        // K_tile landed; all warps past previous PV (reads of Vb)
    __syncthreads();

    // prefetch V_tile into Vb (overlaps S compute)
    #pragma unroll
    for (int i = t; i < 64 * 64; i += 256) {
      const int r = i >> 6, c = (i & 63) * 4;
      cp16(vb_a + (uint32_t)(r * LDQ + c) * 4, xw + (size_t)(tile * 64 + r) * FF + c);
    }
    CP_COMMIT();

    // ---- S = Q K^T : strip rows wr*16, cols wc*32 + {0,16} ----
    wmma::fragment<wmma::accumulator, 16, 16, 8, float> sacc[2];
    wmma::fill_fragment(sacc[0], 0.f);
    wmma::fill_fragment(sacc[1], 0.f);
    #pragma unroll 8
    for (int k = 0; k < 256; k += 8) {
      wmma::fragment<wmma::matrix_a, 16, 16, 8, wmma::precision::tf32, wmma::row_major> af;
      wmma::load_matrix_sync(af, Qs + wr * 16 * LDQ + k, LDQ);
      wmma::fragment<wmma::matrix_b, 16, 16, 8, wmma::precision::tf32, wmma::col_major> bf0, bf1;
      wmma::load_matrix_sync(bf0, Kb + (wc * 32) * LDQ + k, LDQ);
      wmma::load_matrix_sync(bf1, Kb + (wc * 32 + 16) * LDQ + k, LDQ);
      wmma::mma_sync(sacc[0], af, bf0, sacc[0]);
      wmma::mma_sync(sacc[1], af, bf1, sacc[1]);
    }
    wmma::store_matrix_sync(Ps + wr * 16 * LDP + wc * 32, sacc[0], LDP, wmma::mem_row_major);
    wmma::store_matrix_sync(Ps + wr * 16 * LDP + wc * 32 + 16, sacc[1], LDP, wmma::mem_row_major);
    __syncwarp();

    // ---- exp in place (tf32-rounded) + deterministic rowsum ----
    {
      const int r = lane & 15, ch = lane >> 4;
      float* pr = Ps + (wr * 16 + r) * LDP + wc * 32 + ch * 16;
      float s = 0.f;
      #pragma unroll
      for (int c2 = 0; c2 < 16; c2++) {
        float e = wmma::__float_to_tf32(__expf(pr[c2] * SCALE));
        pr[c2] = e;
        s += e;
      }
      s += __shfl_xor_sync(0xffffffff, s, 16);
      if (lane < 16) rsum += s;
    }
    CP_WAIT0();        // V_tile landed
    __syncthreads();   // + P visible to all warps

    // prefetch K_{tile+1} into Kb (overlaps PV compute; wraps harmlessly at end)
    {
      const int jn = ((tile + 1) & 63) * 64;
      #pragma unroll
      for (int i = t; i < 64 * 64; i += 256) {
        const int r = i >> 6, c = (i & 63) * 4;
        cp16(kb_a + (uint32_t)(r * LDQ + c) * 4, xp + (size_t)(jn + r) * FF + c);
      }
      CP_COMMIT();
    }

    // ---- O += P V : A rows wr*16 (k=0..63), B = V row_major, n-half wc*128 ----
    #pragma unroll 4
    for (int k = 0; k < 64; k += 8) {
      wmma::fragment<wmma::matrix_a, 16, 16, 8, wmma::precision::tf32, wmma::row_major> af;
      wmma::load_matrix_sync(af, Ps + wr * 16 * LDP + k, LDP);
      #pragma unroll
      for (int nt = 0; nt < 8; nt++) {
        wmma::fragment<wmma::matrix_b, 16, 16, 8, wmma::precision::tf32, wmma::row_major> bf;
        wmma::load_matrix_sync(bf, Vb + k * LDQ + wc * 128 + nt * 16, LDQ);
        wmma::mma_sync(oacc[nt], af, bf, oacc[nt]);
      }
    }
  }

  // ---- combine rowsum halves ----
  if (lane < 16) rsp[wc * 64 + wr * 16 + lane] = rsum;
  __syncthreads();

  // ---- normalize + write out[:, :, 256:512]; reuse Ps as per-warp staging ----
  float* scr = Ps + w * 340;
  const int r = lane >> 1, c0 = (lane & 1) * 8;
  const float inv = 1.f / (rsp[wr * 16 + r] + rsp[64 + wr * 16 + r]);
  float* orow = out + (size_t)(b * NN + row0 + wr * 16 + r) * (EE + FF) + EE + wc * 128;
  #pragma unroll
  for (int nt = 0; nt < 8; nt++) {
    wmma::store_matrix_sync(scr, oacc[nt], 20, wmma::mem_row_major);
    __syncwarp();
    #pragma unroll
    for (int c2 = 0; c2 < 8; c2++)
      orow[nt * 16 + c0 + c2] = scr[r * 20 + c0 + c2] * inv;
    __syncwarp();
  }
}

// =================================================================================
extern "C" void kernel_launch(void* const* d_in, const int* in_sizes, int n_in,
                              void* d_out, int out_size) {
  const float* x      = (const float*)d_in[0];
  const int*   H      = (const int*)  d_in[1];
  const float* weight = (const float*)d_in[2];
  const float* bias   = (const float*)d_in[3];
  const float* wn_w   = (const float*)d_in[4];
  const float* wn_b   = (const float*)d_in[5];
  const float* m1w    = (const float*)d_in[6];
  const float* m1b    = (const float*)d_in[7];
  const float* m2w    = (const float*)d_in[8];
  const float* m2b    = (const float*)d_in[9];
  const float* m3w    = (const float*)d_in[10];
  const float* m3b    = (const float*)d_in[11];
  const float* cw     = (const float*)d_in[12];
  const float* cb     = (const float*)d_in[13];
  const float* hb     = (const float*)d_in[14];
  const float* alpha  = (const float*)d_in[15];
  float* out = (float*)d_out;

  cudaFuncSetAttribute(gemm_kernel, cudaFuncAttributeMaxDynamicSharedMemorySize, GEMM_SMEM);
  cudaFuncSetAttribute(flash_wmma, cudaFuncAttributeMaxDynamicSharedMemorySize, FL_SMEM);

  edge_kernel<<<MAXE, 256>>>(x, H, m1w, m1b, m2w, m2b, m3w, m3b);
  aw_kernel<<<dim3(NN, BB), 256>>>(x, H, cw, cb, hb, alpha, out);
  gemm_kernel<<<dim3(FF / 64, (BB * NN) / 64, 2), 256, GEMM_SMEM>>>(x, wn_w, wn_b, weight, bias);
  flash_wmma<<<dim3(NN / 64, BB), 256, FL_SMEM>>>(out);
}

// round 7
// speedup vs baseline: 3.2271x; 1.9851x over previous
#include <cuda_runtime.h>
#include <mma.h>
#include <cuda_bf16.h>
#include <math.h>
#include <cstdint>

using namespace nvcuda;

#define BB 4
#define NN 4096
#define EE 256
#define FF 256
#define MAXE 50
#define HH1 128
#define HH2 64
#define SCALE 0.0625f   // 1/sqrt(256)

// ---------------- device scratch ----------------
__device__ __nv_bfloat16 g_xph[BB * NN * FF];  // bf16( x @ Wn_w + Wn_b )
__device__ __nv_bfloat16 g_xwh[BB * NN * FF];  // bf16( x @ weight + bias )
__device__ float g_ctx[BB * 64];
__device__ float g_valid[64];

// ---------------- cp.async helpers ----------------
__device__ __forceinline__ uint32_t smem_u32(const void* p) {
  uint32_t a;
  asm("{ .reg .u64 t; cvta.to.shared.u64 t, %1; cvt.u32.u64 %0, t; }" : "=r"(a) : "l"(p));
  return a;
}
__device__ __forceinline__ void cp16(uint32_t dst, const void* src) {
  asm volatile("cp.async.cg.shared.global [%0], [%1], 16;" ::"r"(dst), "l"(src));
}
#define CP_COMMIT() asm volatile("cp.async.commit_group;" ::: "memory")
#define CP_WAIT0()  asm volatile("cp.async.wait_group 0;" ::: "memory")

// ================= Kernel 1: hyperedge stats + context MLP =================
__global__ void __launch_bounds__(256) edge_kernel(
    const float* __restrict__ x, const int* __restrict__ H,
    const float* __restrict__ m1w, const float* __restrict__ m1b,
    const float* __restrict__ m2w, const float* __restrict__ m2b,
    const float* __restrict__ m3w, const float* __restrict__ m3b) {
  __shared__ float mask[NN];
  __shared__ float red[256];
  __shared__ float meanS[BB][FF];
  __shared__ float h1S[BB][HH1];
  __shared__ float h2S[BB][HH2];
  const int e = blockIdx.x, t = threadIdx.x;
  float dsum = 0.f;
  for (int n = t; n < NN; n += 256) {
    float m = (float)H[n * EE + e];
    mask[n] = m;
    dsum += m;
  }
  red[t] = dsum;
  __syncthreads();
  for (int s = 128; s > 0; s >>= 1) {
    if (t < s) red[t] += red[t + s];
    __syncthreads();
  }
  const float deg = red[0];
  float a0 = 0.f, a1 = 0.f, a2 = 0.f, a3 = 0.f;
  for (int n = 0; n < NN; n++) {
    if (mask[n] != 0.f) {
      a0 += x[(size_t)(0 * NN + n) * FF + t];
      a1 += x[(size_t)(1 * NN + n) * FF + t];
      a2 += x[(size_t)(2 * NN + n) * FF + t];
      a3 += x[(size_t)(3 * NN + n) * FF + t];
    }
  }
  const float inv = 1.f / fmaxf(deg, 1.f);
  meanS[0][t] = a0 * inv; meanS[1][t] = a1 * inv;
  meanS[2][t] = a2 * inv; meanS[3][t] = a3 * inv;
  __syncthreads();
  if (t < HH1) {
    for (int b = 0; b < BB; b++) {
      float s = m1b[t];
      for (int f = 0; f < FF; f++) s += meanS[b][f] * m1w[f * HH1 + t];
      h1S[b][t] = fmaxf(s, 0.f);
    }
  }
  __syncthreads();
  if (t < HH2) {
    for (int b = 0; b < BB; b++) {
      float s = m2b[t];
      for (int p = 0; p < HH1; p++) s += h1S[b][p] * m2w[p * HH2 + t];
      h2S[b][t] = fmaxf(s, 0.f);
    }
  }
  __syncthreads();
  if (t < BB) {
    float s = m3b[0];
    for (int j = 0; j < HH2; j++) s += h2S[t][j] * m3w[j];
    g_ctx[t * 64 + e] = s;
  }
  if (t == 0) g_valid[e] = (deg > 1.f) ? 1.f : 0.f;
}

// ================= Kernel 2: adaptive weights (warp-per-node) =================
__global__ void __launch_bounds__(256) aw_kernel(
    const float* __restrict__ x, const int* __restrict__ H,
    const float* __restrict__ cw, const float* __restrict__ cb,
    const float* __restrict__ hb, const float* __restrict__ alpha,
    float* __restrict__ out) {
  const int w = threadIdx.x >> 5, lane = threadIdx.x & 31;
  const int n = blockIdx.x * 8 + w, b = blockIdx.y;
  const float* xr = x + (size_t)(b * NN + n) * FF;
  float s = 0.f;
  #pragma unroll
  for (int j = 0; j < 8; j++) s += xr[lane + 32 * j] * cw[lane + 32 * j];
  #pragma unroll
  for (int m = 16; m > 0; m >>= 1) s += __shfl_xor_sync(0xffffffff, s, m);
  const float compat = s + cb[0] + hb[0];
  const float al = alpha[0];
  float* orow = out + (size_t)(b * NN + n) * (EE + FF);
  #pragma unroll
  for (int j = 0; j < 8; j++) {
    const int e = lane + 32 * j;
    float o = 0.f;
    if (e < MAXE && H[n * EE + e] != 0 && g_valid[e] != 0.f) {
      float z = compat + al * g_ctx[b * 64 + e];
      o = 1.f / (1.f + __expf(-z));
    }
    orow[e] = o;
  }
}

// ================= Kernel 3: SGEMM; epilogue rounds result to bf16 ============
#define GEMM_SMEM ((256 * 65 + 256 * 64) * 4)
__global__ void __launch_bounds__(256, 1) gemm_kernel(
    const float* __restrict__ x,
    const float* __restrict__ wn_w, const float* __restrict__ wn_b,
    const float* __restrict__ weight, const float* __restrict__ bias) {
  extern __shared__ float sm[];
  float* Xs = sm;
  float* Ws = sm + 256 * 65;
  const float* W; const float* bv; __nv_bfloat16* dst;
  if (blockIdx.z == 0) { W = wn_w;   bv = wn_b; dst = g_xph; }
  else                 { W = weight; bv = bias; dst = g_xwh; }
  const int n0 = blockIdx.x * 64, m0 = blockIdx.y * 64;
  const int t = threadIdx.x, tx = t & 15, ty = t >> 4;
  for (int i = 0; i < 64; i++)
    Xs[t * 65 + i] = x[(size_t)(m0 + i) * FF + t];
  for (int i = 0; i < 64; i++) {
    int idx = t + i * 256; int j = idx & 63; int k = idx >> 6;
    Ws[k * 64 + j] = W[(size_t)k * FF + n0 + j];
  }
  __syncthreads();
  float acc[4][4] = {};
  #pragma unroll 8
  for (int k = 0; k < 256; k++) {
    const float* xr = Xs + k * 65;
    const float* wr = Ws + k * 64;
    float q0 = xr[ty], q1 = xr[ty + 16], q2 = xr[ty + 32], q3 = xr[ty + 48];
    float w0 = wr[tx], w1 = wr[tx + 16], w2 = wr[tx + 32], w3 = wr[tx + 48];
    acc[0][0] += q0 * w0; acc[0][1] += q0 * w1; acc[0][2] += q0 * w2; acc[0][3] += q0 * w3;
    acc[1][0] += q1 * w0; acc[1][1] += q1 * w1; acc[1][2] += q1 * w2; acc[1][3] += q1 * w3;
    acc[2][0] += q2 * w0; acc[2][1] += q2 * w1; acc[2][2] += q2 * w2; acc[2][3] += q2 * w3;
    acc[3][0] += q3 * w0; acc[3][1] += q3 * w1; acc[3][2] += q3 * w2; acc[3][3] += q3 * w3;
  }
  #pragma unroll
  for (int a = 0; a < 4; a++) {
    const int row = m0 + ty + 16 * a;
    #pragma unroll
    for (int c = 0; c < 4; c++) {
      const int col = n0 + tx + 16 * c;
      dst[(size_t)row * FF + col] = __float2bfloat16_rn(acc[a][c] + bv[col]);
    }
  }
}

// ================= Kernel 4: WMMA bf16 flash, cp.async pipelined =================
// 64 Q-rows/CTA, 64 j-tiles of 64.  8 warps: warp w -> row strip (w&3)*16,
// col half (w>>2).  Q/K/V/P in bf16, S/O accumulate fp32.
#define LDQ 264    // bf16 elems per row (528B = 33*16B, conflict-free)
#define LDP 72     // bf16 P row pitch (144B = 9*16B)
#define LDPF 68    // fp32 S row pitch (272B = 17*16B)
#define QB 0
#define KB (64 * LDQ * 2)
#define VB (KB + 64 * LDQ * 2)
#define PFB (VB + 64 * LDQ * 2)            // fp32 S [64][LDPF]
#define PHB (PFB + 64 * LDPF * 4)          // bf16 P [64][LDP]
#define RSB (PHB + 64 * LDP * 2)           // fp32 [2][64]
#define FL_SMEM (RSB + 512)

__global__ void __launch_bounds__(256, 1) flash_wmma(float* __restrict__ out) {
  extern __shared__ char smc[];
  __nv_bfloat16* Qh = (__nv_bfloat16*)(smc + QB);
  __nv_bfloat16* Kh = (__nv_bfloat16*)(smc + KB);
  __nv_bfloat16* Vh = (__nv_bfloat16*)(smc + VB);
  float*         Pf = (float*)(smc + PFB);
  __nv_bfloat16* Ph = (__nv_bfloat16*)(smc + PHB);
  float*         rsp = (float*)(smc + RSB);
  const uint32_t qa = smem_u32(Qh), ka = smem_u32(Kh), va = smem_u32(Vh);
  const int b = blockIdx.y, row0 = blockIdx.x * 64;
  const int t = threadIdx.x, w = t >> 5, lane = t & 31;
  const int wr = w & 3, wc = w >> 2;
  const __nv_bfloat16* xp = g_xph + (size_t)b * NN * FF;
  const __nv_bfloat16* xw = g_xwh + (size_t)b * NN * FF;

  // async: resident Q tile + K tile 0 (rows of 256 bf16 = 32 x 16B chunks)
  #pragma unroll
  for (int i = t; i < 64 * 32; i += 256) {
    const int r = i >> 5, c = (i & 31) * 8;
    const uint32_t off = (uint32_t)(r * LDQ + c) * 2;
    cp16(qa + off, xp + (size_t)(row0 + r) * FF + c);
    cp16(ka + off, xp + (size_t)r * FF + c);
  }
  CP_COMMIT();

  wmma::fragment<wmma::accumulator, 16, 16, 16, float> oacc[8];
  #pragma unroll
  for (int i = 0; i < 8; i++) wmma::fill_fragment(oacc[i], 0.f);
  float rsum = 0.f;  // lanes 0..15: partial rowsum (this col half)

  for (int tile = 0; tile < 64; tile++) {
    CP_WAIT0();
    __syncthreads();

    // prefetch V_tile (overlaps S compute)
    #pragma unroll
    for (int i = t; i < 64 * 32; i += 256) {
      const int r = i >> 5, c = (i & 31) * 8;
      cp16(va + (uint32_t)(r * LDQ + c) * 2, xw + (size_t)(tile * 64 + r) * FF + c);
    }
    CP_COMMIT();

    // ---- S = Q K^T : strip rows wr*16, cols wc*32 + {0,16} ----
    wmma::fragment<wmma::accumulator, 16, 16, 16, float> sacc[2];
    wmma::fill_fragment(sacc[0], 0.f);
    wmma::fill_fragment(sacc[1], 0.f);
    #pragma unroll
    for (int k = 0; k < 256; k += 16) {
      wmma::fragment<wmma::matrix_a, 16, 16, 16, __nv_bfloat16, wmma::row_major> af;
      wmma::load_matrix_sync(af, Qh + wr * 16 * LDQ + k, LDQ);
      wmma::fragment<wmma::matrix_b, 16, 16, 16, __nv_bfloat16, wmma::col_major> bf0, bf1;
      wmma::load_matrix_sync(bf0, Kh + (wc * 32) * LDQ + k, LDQ);
      wmma::load_matrix_sync(bf1, Kh + (wc * 32 + 16) * LDQ + k, LDQ);
      wmma::mma_sync(sacc[0], af, bf0, sacc[0]);
      wmma::mma_sync(sacc[1], af, bf1, sacc[1]);
    }
    wmma::store_matrix_sync(Pf + wr * 16 * LDPF + wc * 32, sacc[0], LDPF, wmma::mem_row_major);
    wmma::store_matrix_sync(Pf + wr * 16 * LDPF + wc * 32 + 16, sacc[1], LDPF, wmma::mem_row_major);
    __syncwarp();

    // ---- P = bf16(exp(S*scale)) + deterministic rowsum ----
    {
      const int r = lane & 15, ch = lane >> 4;
      const float* pr = Pf + (wr * 16 + r) * LDPF + wc * 32 + ch * 16;
      __nv_bfloat16* ph = Ph + (wr * 16 + r) * LDP + wc * 32 + ch * 16;
      float s = 0.f;
      #pragma unroll
      for (int c2 = 0; c2 < 16; c2++) {
        __nv_bfloat16 e = __float2bfloat16_rn(__expf(pr[c2] * SCALE));
        ph[c2] = e;
        s += __bfloat162float(e);
      }
      s += __shfl_xor_sync(0xffffffff, s, 16);
      if (lane < 16) rsum += s;
    }
    CP_WAIT0();        // V_tile landed
    __syncthreads();   // + P visible to all warps

    // prefetch K_{tile+1} (overlaps PV compute)
    {
      const int jn = ((tile + 1) & 63) * 64;
      #pragma unroll
      for (int i = t; i < 64 * 32; i += 256) {
        const int r = i >> 5, c = (i & 31) * 8;
        cp16(ka + (uint32_t)(r * LDQ + c) * 2, xp + (size_t)(jn + r) * FF + c);
      }
      CP_COMMIT();
    }

    // ---- O += P V : A rows wr*16 (k=0..63), B = V row_major, n-half wc*128 ----
    #pragma unroll
    for (int k = 0; k < 64; k += 16) {
      wmma::fragment<wmma::matrix_a, 16, 16, 16, __nv_bfloat16, wmma::row_major> af;
      wmma::load_matrix_sync(af, Ph + wr * 16 * LDP + k, LDP);
      #pragma unroll
      for (int nt = 0; nt < 8; nt++) {
        wmma::fragment<wmma::matrix_b, 16, 16, 16, __nv_bfloat16, wmma::row_major> bf;
        wmma::load_matrix_sync(bf, Vh + k * LDQ + wc * 128 + nt * 16, LDQ);
        wmma::mma_sync(oacc[nt], af, bf, oacc[nt]);
      }
    }
  }

  // ---- combine rowsum halves ----
  if (lane < 16) rsp[wc * 64 + wr * 16 + lane] = rsum;
  __syncthreads();

  // ---- normalize + write out[:, :, 256:512]; Pf as per-warp staging ----
  float* scr = Pf + w * 340;
  const int r = lane >> 1, c0 = (lane & 1) * 8;
  const float inv = 1.f / (rsp[wr * 16 + r] + rsp[64 + wr * 16 + r]);
  float* orow = out + (size_t)(b * NN + row0 + wr * 16 + r) * (EE + FF) + EE + wc * 128;
  #pragma unroll
  for (int nt = 0; nt < 8; nt++) {
    wmma::store_matrix_sync(scr, oacc[nt], 20, wmma::mem_row_major);
    __syncwarp();
    #pragma unroll
    for (int c2 = 0; c2 < 8; c2++)
      orow[nt * 16 + c0 + c2] = scr[r * 20 + c0 + c2] * inv;
    __syncwarp();
  }
}

// =================================================================================
extern "C" void kernel_launch(void* const* d_in, const int* in_sizes, int n_in,
                              void* d_out, int out_size) {
  const float* x      = (const float*)d_in[0];
  const int*   H      = (const int*)  d_in[1];
  const float* weight = (const float*)d_in[2];
  const float* bias   = (const float*)d_in[3];
  const float* wn_w   = (const float*)d_in[4];
  const float* wn_b   = (const float*)d_in[5];
  const float* m1w    = (const float*)d_in[6];
  const float* m1b    = (const float*)d_in[7];
  const float* m2w    = (const float*)d_in[8];
  const float* m2b    = (const float*)d_in[9];
  const float* m3w    = (const float*)d_in[10];
  const float* m3b    = (const float*)d_in[11];
  const float* cw     = (const float*)d_in[12];
  const float* cb     = (const float*)d_in[13];
  const float* hb     = (const float*)d_in[14];
  const float* alpha  = (const float*)d_in[15];
  float* out = (float*)d_out;

  cudaFuncSetAttribute(gemm_kernel, cudaFuncAttributeMaxDynamicSharedMemorySize, GEMM_SMEM);
  cudaFuncSetAttribute(flash_wmma, cudaFuncAttributeMaxDynamicSharedMemorySize, FL_SMEM);

  edge_kernel<<<MAXE, 256>>>(x, H, m1w, m1b, m2w, m2b, m3w, m3b);
  aw_kernel<<<dim3(NN / 8, BB), 256>>>(x, H, cw, cb, hb, alpha, out);
  gemm_kernel<<<dim3(FF / 64, (BB * NN) / 64, 2), 256, GEMM_SMEM>>>(x, wn_w, wn_b, weight, bias);
  flash_wmma<<<dim3(NN / 64, BB), 256, FL_SMEM>>>(out);
}

// round 8
// speedup vs baseline: 3.3765x; 1.0463x over previous
#include <cuda_runtime.h>
#include <mma.h>
#include <cuda_bf16.h>
#include <math.h>
#include <cstdint>

using namespace nvcuda;

#define BB 4
#define NN 4096
#define EE 256
#define FF 256
#define MAXE 50
#define HH1 128
#define HH2 64
#define SCALE 0.0625f   // 1/sqrt(256)

// ---------------- device scratch ----------------
__device__ __nv_bfloat16 g_xph[BB * NN * FF];  // bf16( x @ Wn_w + Wn_b )
__device__ __nv_bfloat16 g_xwh[BB * NN * FF];  // bf16( x @ weight + bias )
__device__ float g_ctx[BB * 64];
__device__ float g_valid[64];

// ---------------- cp.async helpers ----------------
__device__ __forceinline__ uint32_t smem_u32(const void* p) {
  uint32_t a;
  asm("{ .reg .u64 t; cvta.to.shared.u64 t, %1; cvt.u32.u64 %0, t; }" : "=r"(a) : "l"(p));
  return a;
}
__device__ __forceinline__ void cp16(uint32_t dst, const void* src) {
  asm volatile("cp.async.cg.shared.global [%0], [%1], 16;" ::"r"(dst), "l"(src));
}
#define CP_COMMIT() asm volatile("cp.async.commit_group;" ::: "memory")
#define CP_WAIT0()  asm volatile("cp.async.wait_group 0;" ::: "memory")

// ================= Kernel 1: hyperedge stats + context MLP =================
__global__ void __launch_bounds__(256) edge_kernel(
    const float* __restrict__ x, const int* __restrict__ H,
    const float* __restrict__ m1w, const float* __restrict__ m1b,
    const float* __restrict__ m2w, const float* __restrict__ m2b,
    const float* __restrict__ m3w, const float* __restrict__ m3b) {
  __shared__ float mask[NN];
  __shared__ float red[256];
  __shared__ float meanS[BB][FF];
  __shared__ float h1S[BB][HH1];
  __shared__ float h2S[BB][HH2];
  const int e = blockIdx.x, t = threadIdx.x;
  float dsum = 0.f;
  for (int n = t; n < NN; n += 256) {
    float m = (float)H[n * EE + e];
    mask[n] = m;
    dsum += m;
  }
  red[t] = dsum;
  __syncthreads();
  for (int s = 128; s > 0; s >>= 1) {
    if (t < s) red[t] += red[t + s];
    __syncthreads();
  }
  const float deg = red[0];
  float a0 = 0.f, a1 = 0.f, a2 = 0.f, a3 = 0.f;
  for (int n = 0; n < NN; n++) {
    if (mask[n] != 0.f) {
      a0 += x[(size_t)(0 * NN + n) * FF + t];
      a1 += x[(size_t)(1 * NN + n) * FF + t];
      a2 += x[(size_t)(2 * NN + n) * FF + t];
      a3 += x[(size_t)(3 * NN + n) * FF + t];
    }
  }
  const float inv = 1.f / fmaxf(deg, 1.f);
  meanS[0][t] = a0 * inv; meanS[1][t] = a1 * inv;
  meanS[2][t] = a2 * inv; meanS[3][t] = a3 * inv;
  __syncthreads();
  if (t < HH1) {
    for (int b = 0; b < BB; b++) {
      float s = m1b[t];
      for (int f = 0; f < FF; f++) s += meanS[b][f] * m1w[f * HH1 + t];
      h1S[b][t] = fmaxf(s, 0.f);
    }
  }
  __syncthreads();
  if (t < HH2) {
    for (int b = 0; b < BB; b++) {
      float s = m2b[t];
      for (int p = 0; p < HH1; p++) s += h1S[b][p] * m2w[p * HH2 + t];
      h2S[b][t] = fmaxf(s, 0.f);
    }
  }
  __syncthreads();
  if (t < BB) {
    float s = m3b[0];
    for (int j = 0; j < HH2; j++) s += h2S[t][j] * m3w[j];
    g_ctx[t * 64 + e] = s;
  }
  if (t == 0) g_valid[e] = (deg > 1.f) ? 1.f : 0.f;
}

// ================= Kernel 2: adaptive weights (warp-per-node) =================
__global__ void __launch_bounds__(256) aw_kernel(
    const float* __restrict__ x, const int* __restrict__ H,
    const float* __restrict__ cw, const float* __restrict__ cb,
    const float* __restrict__ hb, const float* __restrict__ alpha,
    float* __restrict__ out) {
  const int w = threadIdx.x >> 5, lane = threadIdx.x & 31;
  const int n = blockIdx.x * 8 + w, b = blockIdx.y;
  const float* xr = x + (size_t)(b * NN + n) * FF;
  float s = 0.f;
  #pragma unroll
  for (int j = 0; j < 8; j++) s += xr[lane + 32 * j] * cw[lane + 32 * j];
  #pragma unroll
  for (int m = 16; m > 0; m >>= 1) s += __shfl_xor_sync(0xffffffff, s, m);
  const float compat = s + cb[0] + hb[0];
  const float al = alpha[0];
  float* orow = out + (size_t)(b * NN + n) * (EE + FF);
  #pragma unroll
  for (int j = 0; j < 8; j++) {
    const int e = lane + 32 * j;
    float o = 0.f;
    if (e < MAXE && H[n * EE + e] != 0 && g_valid[e] != 0.f) {
      float z = compat + al * g_ctx[b * 64 + e];
      o = 1.f / (1.f + __expf(-z));
    }
    orow[e] = o;
  }
}

// ================= Kernel 3: WMMA bf16 GEMM  (x@W + b -> bf16) ============
// grid (2, 128, 2): 128x128 output tile per CTA; z selects gemm.
// A = bf16(x) [128,256], B = bf16(W) [256,128]; fp32 accumulate; bias fp32.
#define LDA 264
#define LDB 136
#define G2_SMEM ((128 * LDA + 256 * LDB) * 2)

__global__ void __launch_bounds__(256, 1) gemm_bf16_kernel(
    const float* __restrict__ x,
    const float* __restrict__ wn_w, const float* __restrict__ wn_b,
    const float* __restrict__ weight, const float* __restrict__ bias) {
  extern __shared__ char smc[];
  __nv_bfloat16* Abf = (__nv_bfloat16*)smc;
  __nv_bfloat16* Bbf = Abf + 128 * LDA;
  const float* W; const float* bv; __nv_bfloat16* dst;
  if (blockIdx.z == 0) { W = wn_w;   bv = wn_b; dst = g_xph; }
  else                 { W = weight; bv = bias; dst = g_xwh; }
  const int n0 = blockIdx.x * 128, m0 = blockIdx.y * 128;
  const int t = threadIdx.x, w = t >> 5, lane = t & 31;

  for (int i = t; i < 128 * 256; i += 256) {
    const int r = i >> 8, c = i & 255;
    Abf[r * LDA + c] = __float2bfloat16_rn(x[(size_t)(m0 + r) * FF + c]);
  }
  for (int i = t; i < 256 * 128; i += 256) {
    const int k = i >> 7, j = i & 127;
    Bbf[k * LDB + j] = __float2bfloat16_rn(W[(size_t)k * FF + n0 + j]);
  }
  __syncthreads();

  wmma::fragment<wmma::accumulator, 16, 16, 16, float> oacc[8];
  #pragma unroll
  for (int i = 0; i < 8; i++) wmma::fill_fragment(oacc[i], 0.f);
  #pragma unroll
  for (int k = 0; k < 256; k += 16) {
    wmma::fragment<wmma::matrix_a, 16, 16, 16, __nv_bfloat16, wmma::row_major> af;
    wmma::load_matrix_sync(af, Abf + w * 16 * LDA + k, LDA);
    #pragma unroll
    for (int nt = 0; nt < 8; nt++) {
      wmma::fragment<wmma::matrix_b, 16, 16, 16, __nv_bfloat16, wmma::row_major> bf;
      wmma::load_matrix_sync(bf, Bbf + k * LDB + nt * 16, LDB);
      wmma::mma_sync(oacc[nt], af, bf, oacc[nt]);
    }
  }
  __syncthreads();

  float* scr = (float*)smc + w * 340;
  const int r = lane >> 1, c0 = (lane & 1) * 8;
  #pragma unroll
  for (int nt = 0; nt < 8; nt++) {
    wmma::store_matrix_sync(scr, oacc[nt], 20, wmma::mem_row_major);
    __syncwarp();
    #pragma unroll
    for (int c2 = 0; c2 < 8; c2++) {
      const int col = n0 + nt * 16 + c0 + c2;
      dst[(size_t)(m0 + w * 16 + r) * FF + col] =
          __float2bfloat16_rn(scr[r * 20 + c0 + c2] + bv[col]);
    }
    __syncwarp();
  }
}

// ================= Kernel 4: WMMA bf16 flash, 512 threads / 16 warps ============
// 64 Q-rows/CTA, 64 j-tiles of 64.  warp w: row strip wr=w&3 (16 rows),
// quarter wq=w>>2 (S cols wq*16, O cols wq*64).  oacc[4] -> <=128 regs.
#define LDQ 264    // bf16 pitch (528B)
#define LDP 72     // bf16 P pitch (144B)
#define LDPF 68    // fp32 S pitch (272B)
#define QB 0
#define KB (64 * LDQ * 2)
#define VB (KB + 64 * LDQ * 2)
#define PFB (VB + 64 * LDQ * 2)            // fp32 S [64][LDPF]
#define PHB (PFB + 64 * LDPF * 4)          // bf16 P [64][LDP]
#define RSB (PHB + 64 * LDP * 2)           // fp32 [4][64]
#define FL_SMEM (RSB + 1024 + 256)

__global__ void __launch_bounds__(512, 1) flash_wmma(float* __restrict__ out) {
  extern __shared__ char smc[];
  __nv_bfloat16* Qh = (__nv_bfloat16*)(smc + QB);
  __nv_bfloat16* Kh = (__nv_bfloat16*)(smc + KB);
  __nv_bfloat16* Vh = (__nv_bfloat16*)(smc + VB);
  float*         Pf = (float*)(smc + PFB);
  __nv_bfloat16* Ph = (__nv_bfloat16*)(smc + PHB);
  float*         rsp = (float*)(smc + RSB);
  const uint32_t qa = smem_u32(Qh), ka = smem_u32(Kh), va = smem_u32(Vh);
  const int b = blockIdx.y, row0 = blockIdx.x * 64;
  const int t = threadIdx.x, w = t >> 5, lane = t & 31;
  const int wr = w & 3, wq = w >> 2;
  const __nv_bfloat16* xp = g_xph + (size_t)b * NN * FF;
  const __nv_bfloat16* xw = g_xwh + (size_t)b * NN * FF;

  #pragma unroll
  for (int i = t; i < 64 * 32; i += 512) {
    const int r = i >> 5, c = (i & 31) * 8;
    const uint32_t off = (uint32_t)(r * LDQ + c) * 2;
    cp16(qa + off, xp + (size_t)(row0 + r) * FF + c);
    cp16(ka + off, xp + (size_t)r * FF + c);
  }
  CP_COMMIT();

  wmma::fragment<wmma::accumulator, 16, 16, 16, float> oacc[4];
  #pragma unroll
  for (int i = 0; i < 4; i++) wmma::fill_fragment(oacc[i], 0.f);
  float rsum = 0.f;  // lanes 0..15: rowsum partial for row wr*16+lane, quarter wq

  for (int tile = 0; tile < 64; tile++) {
    CP_WAIT0();
    __syncthreads();

    // prefetch V_tile (overlaps S compute)
    #pragma unroll
    for (int i = t; i < 64 * 32; i += 512) {
      const int r = i >> 5, c = (i & 31) * 8;
      cp16(va + (uint32_t)(r * LDQ + c) * 2, xw + (size_t)(tile * 64 + r) * FF + c);
    }
    CP_COMMIT();

    // ---- S = Q K^T : warp tile = rows wr*16, cols wq*16 ----
    wmma::fragment<wmma::accumulator, 16, 16, 16, float> sacc;
    wmma::fill_fragment(sacc, 0.f);
    #pragma unroll
    for (int k = 0; k < 256; k += 16) {
      wmma::fragment<wmma::matrix_a, 16, 16, 16, __nv_bfloat16, wmma::row_major> af;
      wmma::fragment<wmma::matrix_b, 16, 16, 16, __nv_bfloat16, wmma::col_major> bf;
      wmma::load_matrix_sync(af, Qh + wr * 16 * LDQ + k, LDQ);
      wmma::load_matrix_sync(bf, Kh + (wq * 16) * LDQ + k, LDQ);
      wmma::mma_sync(sacc, af, bf, sacc);
    }
    wmma::store_matrix_sync(Pf + wr * 16 * LDPF + wq * 16, sacc, LDPF, wmma::mem_row_major);
    __syncwarp();

    // ---- P = bf16(exp(S*scale)) + rowsum partial (8 elems / lane) ----
    {
      const int r = lane & 15, half = lane >> 4;
      const float* pr = Pf + (wr * 16 + r) * LDPF + wq * 16 + half * 8;
      __nv_bfloat16* ph = Ph + (wr * 16 + r) * LDP + wq * 16 + half * 8;
      float s = 0.f;
      #pragma unroll
      for (int c2 = 0; c2 < 8; c2++) {
        __nv_bfloat16 e = __float2bfloat16_rn(__expf(pr[c2] * SCALE));
        ph[c2] = e;
        s += __bfloat162float(e);
      }
      s += __shfl_xor_sync(0xffffffff, s, 16);
      if (lane < 16) rsum += s;
    }
    CP_WAIT0();        // V_tile landed
    __syncthreads();   // + P visible to all warps

    // prefetch K_{tile+1} (overlaps PV compute)
    {
      const int jn = ((tile + 1) & 63) * 64;
      #pragma unroll
      for (int i = t; i < 64 * 32; i += 512) {
        const int r = i >> 5, c = (i & 31) * 8;
        cp16(ka + (uint32_t)(r * LDQ + c) * 2, xp + (size_t)(jn + r) * FF + c);
      }
      CP_COMMIT();
    }

    // ---- O += P V : A rows wr*16 (k=0..63), B cols wq*64..+64 ----
    #pragma unroll
    for (int k = 0; k < 64; k += 16) {
      wmma::fragment<wmma::matrix_a, 16, 16, 16, __nv_bfloat16, wmma::row_major> af;
      wmma::load_matrix_sync(af, Ph + wr * 16 * LDP + k, LDP);
      #pragma unroll
      for (int nt = 0; nt < 4; nt++) {
        wmma::fragment<wmma::matrix_b, 16, 16, 16, __nv_bfloat16, wmma::row_major> bf;
        wmma::load_matrix_sync(bf, Vh + k * LDQ + wq * 64 + nt * 16, LDQ);
        wmma::mma_sync(oacc[nt], af, bf, oacc[nt]);
      }
    }
  }

  // ---- publish rowsum partials (4 quarters x 64 rows) ----
  if (lane < 16) rsp[wq * 64 + wr * 16 + lane] = rsum;
  __syncthreads();

  // ---- normalize + write out[:, :, 256:512]; scratch carved from Pf/Ph ----
  float* scr = (float*)(smc + PFB) + w * 340;
  const int r = lane >> 1, c0 = (lane & 1) * 8;
  const int row = wr * 16 + r;
  const float inv = 1.f / (rsp[row] + rsp[64 + row] + rsp[128 + row] + rsp[192 + row]);
  float* orow = out + (size_t)(b * NN + row0 + row) * (EE + FF) + EE + wq * 64;
  #pragma unroll
  for (int nt = 0; nt < 4; nt++) {
    wmma::store_matrix_sync(scr, oacc[nt], 20, wmma::mem_row_major);
    __syncwarp();
    #pragma unroll
    for (int c2 = 0; c2 < 8; c2++)
      orow[nt * 16 + c0 + c2] = scr[r * 20 + c0 + c2] * inv;
    __syncwarp();
  }
}

// =================================================================================
extern "C" void kernel_launch(void* const* d_in, const int* in_sizes, int n_in,
                              void* d_out, int out_size) {
  const float* x      = (const float*)d_in[0];
  const int*   H      = (const int*)  d_in[1];
  const float* weight = (const float*)d_in[2];
  const float* bias   = (const float*)d_in[3];
  const float* wn_w   = (const float*)d_in[4];
  const float* wn_b   = (const float*)d_in[5];
  const float* m1w    = (const float*)d_in[6];
  const float* m1b    = (const float*)d_in[7];
  const float* m2w    = (const float*)d_in[8];
  const float* m2b    = (const float*)d_in[9];
  const float* m3w    = (const float*)d_in[10];
  const float* m3b    = (const float*)d_in[11];
  const float* cw     = (const float*)d_in[12];
  const float* cb     = (const float*)d_in[13];
  const float* hb     = (const float*)d_in[14];
  const float* alpha  = (const float*)d_in[15];
  float* out = (float*)d_out;

  cudaFuncSetAttribute(gemm_bf16_kernel, cudaFuncAttributeMaxDynamicSharedMemorySize, G2_SMEM);
  cudaFuncSetAttribute(flash_wmma, cudaFuncAttributeMaxDynamicSharedMemorySize, FL_SMEM);

  edge_kernel<<<MAXE, 256>>>(x, H, m1w, m1b, m2w, m2b, m3w, m3b);
  aw_kernel<<<dim3(NN / 8, BB), 256>>>(x, H, cw, cb, hb, alpha, out);
  gemm_bf16_kernel<<<dim3(2, 128, 2), 256, G2_SMEM>>>(x, wn_w, wn_b, weight, bias);
  flash_wmma<<<dim3(NN / 64, BB), 512, FL_SMEM>>>(out);
}